// round 7
// baseline (speedup 1.0000x reference)
#include <cuda_runtime.h>
#include <math.h>

#define HID   512
#define VOCAB 50000
#define BATCH 64
#define SRC   50
#define STEPS 31
#define NBLK  782   /* ceil(50000/64) */

typedef unsigned long long ull;

// ---------------- persistent device state (no allocations allowed) ----------
__device__ float g_h[BATCH * HID];      // post-attention hidden (carry)
__device__ float g_c[BATCH * HID];      // post-attention cell   (carry)
__device__ float g_hrnn[BATCH * HID];   // raw LSTM outputs this step
__device__ float g_crnn[BATCH * HID];
__device__ int   g_tok[BATCH];
__device__ float g_pmax[NBLK * BATCH];
__device__ int   g_pidx[NBLK * BATCH];

// ---------------- f32x2 packed-FMA helpers (Blackwell dual fp32 pipe) -------
__device__ __forceinline__ ull pack2(float x, float y) {
    ull r; asm("mov.b64 %0, {%1,%2};" : "=l"(r) : "f"(x), "f"(y)); return r;
}
__device__ __forceinline__ void unpack2(ull a, float& x, float& y) {
    asm("mov.b64 {%0,%1}, %2;" : "=f"(x), "=f"(y) : "l"(a));
}
__device__ __forceinline__ ull fma2(ull a, ull b, ull c) {
    ull d; asm("fma.rn.f32x2 %0, %1, %2, %3;" : "=l"(d) : "l"(a), "l"(b), "l"(c)); return d;
}
__device__ __forceinline__ float sigmoidf_(float x) { return 1.f / (1.f + expf(-x)); }

// ---------------- init: copy h0/c0/init_tokens into state -------------------
__global__ void k_init(const float* __restrict__ h0, const float* __restrict__ c0,
                       const int* __restrict__ t0) {
    int tid = blockIdx.x * blockDim.x + threadIdx.x;
    for (int i = tid; i < BATCH * HID; i += blockDim.x * gridDim.x) {
        g_h[i] = h0[i];
        g_c[i] = c0[i];
    }
    if (tid < BATCH) g_tok[tid] = t0[tid];
}

// ---------------- LSTM cell: embed lookup + gates GEMM + cell update --------
// grid 64 blocks (each owns 8 hidden dims across all 4 gates = 32 gate rows),
// 128 threads. f32x2 packs batch pairs. Torch gate order i,f,g,o.
__global__ void k_lstm(const float* __restrict__ embed,
                       const float* __restrict__ w_ih,
                       const float* __restrict__ w_hh,
                       const float* __restrict__ b_ih,
                       const float* __restrict__ b_hh) {
    __shared__ __align__(16) float wi_sm[32 * 33];
    __shared__ __align__(16) float wh_sm[32 * 33];
    __shared__ __align__(16) float x_sm[32 * 66];   // [k][b], padded stride 66
    __shared__ __align__(16) float h_sm[32 * 66];
    __shared__ __align__(16) float gate_sm[32 * 64]; // [r][b]
    __shared__ int tok_sm[BATCH];

    const int tid = threadIdx.x;
    const int d0  = blockIdx.x * 8;
    if (tid < BATCH) tok_sm[tid] = g_tok[tid];

    const int rg2 = tid & 15;   // 16 row-pair groups
    const int bq  = tid >> 4;   // 8 batch-quad groups (4 bpairs each)
    const int r0 = rg2 * 2, r1 = r0 + 1;
    const int j0 = (r0 >> 3) * HID + d0 + (r0 & 7);
    const int j1 = (r1 >> 3) * HID + d0 + (r1 & 7);
    const float bias0 = b_ih[j0] + b_hh[j0];
    const float bias1 = b_ih[j1] + b_hh[j1];

    ull acc0[4], acc1[4];
#pragma unroll
    for (int i = 0; i < 4; i++) { acc0[i] = pack2(bias0, bias0); acc1[i] = pack2(bias1, bias1); }

    __syncthreads();
    for (int k0 = 0; k0 < HID; k0 += 32) {
        for (int i = tid; i < 1024; i += 128) {            // 32 rows x 32 k
            int r = i >> 5, k = i & 31;
            int j = (r >> 3) * HID + d0 + (r & 7);
            wi_sm[r * 33 + k] = w_ih[j * HID + k0 + k];
            wh_sm[r * 33 + k] = w_hh[j * HID + k0 + k];
        }
        for (int i = tid; i < 2048; i += 128) {            // 64 b x 32 k, transpose
            int b = i >> 5, k = i & 31;
            x_sm[k * 66 + b] = embed[tok_sm[b] * HID + k0 + k];
            h_sm[k * 66 + b] = g_h[b * HID + k0 + k];
        }
        __syncthreads();
#pragma unroll 4
        for (int k = 0; k < 32; k++) {
            float wi0 = wi_sm[r0 * 33 + k], wi1 = wi_sm[r1 * 33 + k];
            float wh0 = wh_sm[r0 * 33 + k], wh1 = wh_sm[r1 * 33 + k];
            ull wi02 = pack2(wi0, wi0), wi12 = pack2(wi1, wi1);
            ull wh02 = pack2(wh0, wh0), wh12 = pack2(wh1, wh1);
            const ull* xr = (const ull*)&x_sm[k * 66];
            const ull* hr = (const ull*)&h_sm[k * 66];
#pragma unroll
            for (int i = 0; i < 4; i++) {
                int bp = bq * 4 + i;
                ull x2 = xr[bp], h2 = hr[bp];
                acc0[i] = fma2(wi02, x2, acc0[i]);
                acc0[i] = fma2(wh02, h2, acc0[i]);
                acc1[i] = fma2(wi12, x2, acc1[i]);
                acc1[i] = fma2(wh12, h2, acc1[i]);
            }
        }
        __syncthreads();
    }
#pragma unroll
    for (int i = 0; i < 4; i++) {
        int bp = bq * 4 + i;
        *(ull*)&gate_sm[r0 * 64 + 2 * bp] = acc0[i];
        *(ull*)&gate_sm[r1 * 64 + 2 * bp] = acc1[i];
    }
    __syncthreads();
    // cell update for this block's 8 hidden dims x 64 batches
    for (int i = tid; i < 512; i += 128) {
        int dd = i >> 6, b = i & 63;
        float ig = sigmoidf_(gate_sm[(dd) * 64 + b]);        // i: rows 0..7
        float fg = sigmoidf_(gate_sm[(8 + dd) * 64 + b]);    // f
        float gg = tanhf(gate_sm[(16 + dd) * 64 + b]);       // g
        float og = sigmoidf_(gate_sm[(24 + dd) * 64 + b]);   // o
        int idx = b * HID + d0 + dd;
        float cn = fg * g_c[idx] + ig * gg;
        float hr = og * tanhf(cn);
        g_crnn[idx] = cn;
        g_hrnn[idx] = hr;
    }
}

// ---------------- attention (h and c), residual add, writes carry -----------
// grid 128 = (batch 64) x (which: 0=h, 1=c); 128 threads.
__global__ void k_attn(const float* __restrict__ enc) {
    __shared__ float vv[HID];
    __shared__ float sc[SRC];
    __shared__ float isum_sh;
    const int tid   = threadIdx.x;
    const int bi    = blockIdx.x & 63;
    const int which = blockIdx.x >> 6;
    const float* vr = (which ? g_crnn : g_hrnn) + bi * HID;
    for (int d = tid; d < HID; d += 128) vv[d] = vr[d];
    __syncthreads();
    int warp = tid >> 5, lane = tid & 31;
    for (int s = warp; s < SRC; s += 4) {
        float a = 0.f;
        const float* er = enc + (s * BATCH + bi) * HID;
        for (int d = lane; d < HID; d += 32) a += er[d] * vv[d];
#pragma unroll
        for (int o = 16; o > 0; o >>= 1) a += __shfl_xor_sync(0xffffffffu, a, o);
        if (lane == 0) sc[s] = a * 0.04419417382415922f;  // 1/sqrt(512)
    }
    __syncthreads();
    if (tid == 0) {
        float m = sc[0];
        for (int s = 1; s < SRC; s++) m = fmaxf(m, sc[s]);
        float sum = 0.f;
        for (int s = 0; s < SRC; s++) { float e = expf(sc[s] - m); sc[s] = e; sum += e; }
        isum_sh = 1.f / sum;
    }
    __syncthreads();
    float isum = isum_sh;
    float* dst = (which ? g_c : g_h) + bi * HID;
    for (int d = tid; d < HID; d += 128) {
        float a = 0.f;
#pragma unroll 10
        for (int s = 0; s < SRC; s++) a += sc[s] * enc[(s * BATCH + bi) * HID + d];
        dst[d] = a * isum + vv[d];  // residual
    }
}

// ---------------- logits head: [64 vocab rows] x [64 batches] per block -----
// f32x2 packs batch pairs; fused per-block argmax partials; writes logits.
__global__ void k_logits(const float* __restrict__ embed,
                         const float* __restrict__ fc_bias,
                         float* __restrict__ out_step) {
    __shared__ __align__(16) float e_sm[64 * 65];   // [v][k]
    __shared__ __align__(16) float h_sm[64 * 66];   // [k][b] transposed
    __shared__ float cand_v[64 * 16];
    __shared__ int   cand_i[64 * 16];
    const int tid   = threadIdx.x;                  // 256
    const int vbase = blockIdx.x * 64;
    const int vg = tid & 15;                        // 4 vocab rows each
    const int bg = tid >> 4;                        // 2 batch pairs each

    ull acc[4][2];
#pragma unroll
    for (int iv = 0; iv < 4; iv++) {
        int v = vbase + vg * 4 + iv;
        float bz = (v < VOCAB) ? fc_bias[v] : 0.f;
        acc[iv][0] = pack2(bz, bz);
        acc[iv][1] = pack2(bz, bz);
    }
    for (int k0 = 0; k0 < HID; k0 += 64) {
        for (int i = tid; i < 4096; i += 256) {
            int v = i >> 6, k = i & 63;
            int gv = vbase + v;
            e_sm[v * 65 + k] = (gv < VOCAB) ? embed[gv * HID + k0 + k] : 0.f;
        }
        for (int i = tid; i < 4096; i += 256) {
            int b = i >> 6, k = i & 63;
            h_sm[k * 66 + b] = g_hrnn[b * HID + k0 + k];
        }
        __syncthreads();
#pragma unroll 4
        for (int k = 0; k < 64; k++) {
            float e0 = e_sm[(vg * 4 + 0) * 65 + k];
            float e1 = e_sm[(vg * 4 + 1) * 65 + k];
            float e2 = e_sm[(vg * 4 + 2) * 65 + k];
            float e3 = e_sm[(vg * 4 + 3) * 65 + k];
            const ull* hr = (const ull*)&h_sm[k * 66];
            ull h2a = hr[bg * 2 + 0], h2b = hr[bg * 2 + 1];
            ull e02 = pack2(e0, e0), e12 = pack2(e1, e1);
            ull e22 = pack2(e2, e2), e32 = pack2(e3, e3);
            acc[0][0] = fma2(e02, h2a, acc[0][0]);  acc[0][1] = fma2(e02, h2b, acc[0][1]);
            acc[1][0] = fma2(e12, h2a, acc[1][0]);  acc[1][1] = fma2(e12, h2b, acc[1][1]);
            acc[2][0] = fma2(e22, h2a, acc[2][0]);  acc[2][1] = fma2(e22, h2b, acc[2][1]);
            acc[3][0] = fma2(e32, h2a, acc[3][0]);  acc[3][1] = fma2(e32, h2b, acc[3][1]);
        }
        __syncthreads();
    }
    // write logits + per-thread argmax candidates (v ascending -> first-max tie rule)
    float bb[4]; int ii[4];
#pragma unroll
    for (int q = 0; q < 4; q++) { bb[q] = -3.402823466e38f; ii[q] = 0x7fffffff; }
#pragma unroll
    for (int iv = 0; iv < 4; iv++) {
        int v = vbase + vg * 4 + iv;
#pragma unroll
        for (int j = 0; j < 2; j++) {
            float lx, ly; unpack2(acc[iv][j], lx, ly);
            int bp = bg * 2 + j;
            if (v < VOCAB) {
                out_step[(2 * bp) * VOCAB + v]     = lx;
                out_step[(2 * bp + 1) * VOCAB + v] = ly;
                if (lx > bb[2 * j])     { bb[2 * j]     = lx; ii[2 * j]     = v; }
                if (ly > bb[2 * j + 1]) { bb[2 * j + 1] = ly; ii[2 * j + 1] = v; }
            }
        }
    }
#pragma unroll
    for (int j = 0; j < 2; j++) {
        int bp = bg * 2 + j;
        cand_v[(2 * bp) * 16 + vg]     = bb[2 * j];     cand_i[(2 * bp) * 16 + vg]     = ii[2 * j];
        cand_v[(2 * bp + 1) * 16 + vg] = bb[2 * j + 1]; cand_i[(2 * bp + 1) * 16 + vg] = ii[2 * j + 1];
    }
    __syncthreads();
    if (tid < 64) {
        float bv = cand_v[tid * 16 + 0];
        int   bx = cand_i[tid * 16 + 0];
        for (int g = 1; g < 16; g++) {
            float v = cand_v[tid * 16 + g];
            if (v > bv) { bv = v; bx = cand_i[tid * 16 + g]; }  // vg ascending => first occurrence kept
        }
        g_pmax[blockIdx.x * 64 + tid] = bv;
        g_pidx[blockIdx.x * 64 + tid] = bx;
    }
}

// ---------------- final argmax reduce -> next token + token output ----------
__global__ void k_argmax(float* __restrict__ out_tok, int step, int write_tok) {
    __shared__ float sv[256];
    __shared__ int   si[256];
    const int tid = threadIdx.x;
    const int b = tid & 63, grp = tid >> 6;  // 4 groups per batch
    float bv = -3.402823466e38f;
    int   bx = 0x7fffffff;
    for (int p = grp; p < NBLK; p += 4) {
        float v = g_pmax[p * 64 + b];
        int  ix = g_pidx[p * 64 + b];
        if (v > bv || (v == bv && ix < bx)) { bv = v; bx = ix; }
    }
    sv[tid] = bv; si[tid] = bx;
    __syncthreads();
    if (tid < 64) {
        for (int g = 1; g < 4; g++) {
            float v = sv[tid + 64 * g];
            int  ix = si[tid + 64 * g];
            if (v > bv || (v == bv && ix < bx)) { bv = v; bx = ix; }
        }
        g_tok[b] = bx;
        if (write_tok) out_tok[b * STEPS + step] = (float)bx;  // word_ind.T layout [B, STEPS]
    }
}

// ---------------- launch: 1 init + 31 x (lstm, attn, logits, argmax) --------
extern "C" void kernel_launch(void* const* d_in, const int* in_sizes, int n_in,
                              void* d_out, int out_size) {
    const float* embed   = (const float*)d_in[0];
    const float* fc_bias = (const float*)d_in[1];
    const float* w_ih    = (const float*)d_in[2];
    const float* w_hh    = (const float*)d_in[3];
    const float* b_ih    = (const float*)d_in[4];
    const float* b_hh    = (const float*)d_in[5];
    const float* enc     = (const float*)d_in[6];
    const float* h0      = (const float*)d_in[7];
    const float* c0      = (const float*)d_in[8];
    const int*   t0      = (const int*)d_in[9];
    float* out = (float*)d_out;

    const long long LT = (long long)STEPS * BATCH * VOCAB;  // 99,200,000
    int write_tok = ((long long)out_size >= LT + (long long)BATCH * STEPS) ? 1 : 0;
    float* out_tok = out + LT;

    k_init<<<32, 256>>>(h0, c0, t0);
    for (int t = 0; t < STEPS; t++) {
        k_lstm<<<64, 128>>>(embed, w_ih, w_hh, b_ih, b_hh);
        k_attn<<<128, 128>>>(enc);
        k_logits<<<NBLK, 256>>>(embed, fc_bias, out + (long long)t * BATCH * VOCAB);
        k_argmax<<<1, 256>>>(out_tok, t, write_tok);
    }
}

// round 11
// speedup vs baseline: 1.5785x; 1.5785x over previous
#include <cuda_runtime.h>
#include <math.h>

#define HID   512
#define VOCAB 50000
#define BATCH 64
#define SRC   50
#define STEPS 31
#define VT    128                 /* vocab tile per logits block */
#define NLOG  391                 /* ceil(50000/128) */
#define KT    32                  /* k tile */
#define NEG_INF (-3.402823466e38f)

typedef unsigned long long ull;

// ---------------- persistent device state (no allocations allowed) ----------
__device__ __align__(16) float g_h[BATCH * HID];      // post-attention hidden (carry)
__device__ __align__(16) float g_c[BATCH * HID];      // post-attention cell   (carry)
__device__ __align__(16) float g_hrnn[BATCH * HID];   // raw LSTM outputs this step
__device__ __align__(16) float g_crnn[BATCH * HID];
__device__ int   g_tok[BATCH];
__device__ float g_pmax[NLOG * BATCH];
__device__ int   g_pidx[NLOG * BATCH];
__device__ int   g_done;

// ---------------- f32x2 packed-FMA helpers (Blackwell dual fp32 pipe) -------
__device__ __forceinline__ ull pack2(float x, float y) {
    ull r; asm("mov.b64 %0, {%1,%2};" : "=l"(r) : "f"(x), "f"(y)); return r;
}
__device__ __forceinline__ void unpack2(ull a, float& x, float& y) {
    asm("mov.b64 {%0,%1}, %2;" : "=f"(x), "=f"(y) : "l"(a));
}
__device__ __forceinline__ ull fma2(ull a, ull b, ull c) {
    ull d; asm("fma.rn.f32x2 %0, %1, %2, %3;" : "=l"(d) : "l"(a), "l"(b), "l"(c)); return d;
}
__device__ __forceinline__ float sigmoidf_(float x) { return 1.f / (1.f + expf(-x)); }

// ---------------- init ------------------------------------------------------
__global__ void k_init(const float* __restrict__ h0, const float* __restrict__ c0,
                       const int* __restrict__ t0) {
    int tid = blockIdx.x * blockDim.x + threadIdx.x;
    for (int i = tid; i < BATCH * HID; i += blockDim.x * gridDim.x) {
        g_h[i] = h0[i];
        g_c[i] = c0[i];
    }
    if (tid < BATCH) g_tok[tid] = t0[tid];
    if (tid == 0) g_done = 0;
}

// ---------------- LSTM cell -------------------------------------------------
// 64 blocks x 256 threads. Block owns 8 hidden dims across 4 gates = 32 rows.
// lane = gate row, warp owns 8 batches. Dup'd weight smem kills per-k packs.
__global__ void __launch_bounds__(256) k_lstm(const float* __restrict__ embed,
                       const float* __restrict__ w_ih,
                       const float* __restrict__ w_hh,
                       const float* __restrict__ b_ih,
                       const float* __restrict__ b_hh) {
    __shared__ ull   wi_d[KT][32];     // dup'd pairs, 8KB
    __shared__ ull   wh_d[KT][32];     // 8KB
    __shared__ float x_sm[KT][64];     // 8KB
    __shared__ float hs_sm[KT][64];    // 8KB
    __shared__ float gate_sm[32][64];  // 8KB
    __shared__ int   tok_sm[BATCH];

    const int tid  = threadIdx.x;
    const int lane = tid & 31;
    const int warp = tid >> 5;          // 0..7, owns batches 8w..8w+7
    const int d0   = blockIdx.x * 8;

    if (tid < BATCH) tok_sm[tid] = g_tok[tid];

    const int j = (lane >> 3) * HID + d0 + (lane & 7);  // gate row in [4H]
    const float bias = b_ih[j] + b_hh[j];
    ull acc[4];
#pragma unroll
    for (int bp = 0; bp < 4; bp++) acc[bp] = pack2(bias, bias);

    // fill-role indices
    const int fr  = tid & 31;          // weight row
    const int fk8 = tid >> 5;          // 8 k-quads of 4
    const int jf  = (fr >> 3) * HID + d0 + (fr & 7);
    const int fb  = tid & 63;          // batch
    const int fkq = tid >> 6;          // 4 k-groups of 8
    __syncthreads();

    for (int k0 = 0; k0 < HID; k0 += KT) {
        {   // weights -> dup'd [k][r]
            float4 wi = *(const float4*)(w_ih + (size_t)jf * HID + k0 + fk8 * 4);
            float4 wh = *(const float4*)(w_hh + (size_t)jf * HID + k0 + fk8 * 4);
            wi_d[fk8 * 4 + 0][fr] = pack2(wi.x, wi.x);
            wi_d[fk8 * 4 + 1][fr] = pack2(wi.y, wi.y);
            wi_d[fk8 * 4 + 2][fr] = pack2(wi.z, wi.z);
            wi_d[fk8 * 4 + 3][fr] = pack2(wi.w, wi.w);
            wh_d[fk8 * 4 + 0][fr] = pack2(wh.x, wh.x);
            wh_d[fk8 * 4 + 1][fr] = pack2(wh.y, wh.y);
            wh_d[fk8 * 4 + 2][fr] = pack2(wh.z, wh.z);
            wh_d[fk8 * 4 + 3][fr] = pack2(wh.w, wh.w);
        }
        {   // x (embedding rows) and h -> [k][b]
            const float4* xs = (const float4*)(embed + (size_t)tok_sm[fb] * HID + k0 + fkq * 8);
            const float4* hs = (const float4*)(g_h + (size_t)fb * HID + k0 + fkq * 8);
#pragma unroll
            for (int jj = 0; jj < 2; jj++) {
                float4 fx = xs[jj], fh = hs[jj];
                x_sm [fkq * 8 + 4 * jj + 0][fb] = fx.x;
                x_sm [fkq * 8 + 4 * jj + 1][fb] = fx.y;
                x_sm [fkq * 8 + 4 * jj + 2][fb] = fx.z;
                x_sm [fkq * 8 + 4 * jj + 3][fb] = fx.w;
                hs_sm[fkq * 8 + 4 * jj + 0][fb] = fh.x;
                hs_sm[fkq * 8 + 4 * jj + 1][fb] = fh.y;
                hs_sm[fkq * 8 + 4 * jj + 2][fb] = fh.z;
                hs_sm[fkq * 8 + 4 * jj + 3][fb] = fh.w;
            }
        }
        __syncthreads();
#pragma unroll 8
        for (int k = 0; k < KT; k++) {
            ull wi = wi_d[k][lane];
            ull wh = wh_d[k][lane];
            ulonglong2 xA = *(const ulonglong2*)&x_sm [k][8 * warp];
            ulonglong2 xB = *(const ulonglong2*)&x_sm [k][8 * warp + 4];
            ulonglong2 hA = *(const ulonglong2*)&hs_sm[k][8 * warp];
            ulonglong2 hB = *(const ulonglong2*)&hs_sm[k][8 * warp + 4];
            acc[0] = fma2(wi, xA.x, acc[0]); acc[0] = fma2(wh, hA.x, acc[0]);
            acc[1] = fma2(wi, xA.y, acc[1]); acc[1] = fma2(wh, hA.y, acc[1]);
            acc[2] = fma2(wi, xB.x, acc[2]); acc[2] = fma2(wh, hB.x, acc[2]);
            acc[3] = fma2(wi, xB.y, acc[3]); acc[3] = fma2(wh, hB.y, acc[3]);
        }
        __syncthreads();
    }
#pragma unroll
    for (int bp = 0; bp < 4; bp++)
        *(ull*)&gate_sm[lane][8 * warp + 2 * bp] = acc[bp];
    __syncthreads();
    // cell update: 8 hidden dims x 64 batches
    for (int i = tid; i < 512; i += 256) {
        int dd = i >> 6, b = i & 63;
        float ig = sigmoidf_(gate_sm[dd][b]);
        float fg = sigmoidf_(gate_sm[8 + dd][b]);
        float gg = tanhf(gate_sm[16 + dd][b]);
        float og = sigmoidf_(gate_sm[24 + dd][b]);
        int idx = b * HID + d0 + dd;
        float cn = fg * g_c[idx] + ig * gg;
        g_crnn[idx] = cn;
        g_hrnn[idx] = og * tanhf(cn);
    }
}

// ---------------- fused: logits(+argmax partials) | attention | final argmax
struct SmLogits { ull e[2][KT][64]; float h[KT][64]; };    // 32KB + 8KB
struct SmAttn   { float vv[HID]; float sc[64]; float isum; };
struct SmAmax   { float sv[256]; int si[256]; };
union SmU { SmLogits l; SmAttn a; SmAmax m; };

__global__ void __launch_bounds__(256) k_fused(
        const float* __restrict__ embed, const float* __restrict__ fc_bias,
        const float* __restrict__ enc, float* __restrict__ out_step,
        float* __restrict__ out_tok, int step, int write_tok) {
    __shared__ SmU sm;
    __shared__ int s_last;

    const int tid  = threadIdx.x;
    const int lane = tid & 31;
    const int warp = tid >> 5;
    const int bid  = blockIdx.x;

    if (bid < NLOG) {
        // ================= logits block: 128 vocab x 64 batch =================
        const int vbase = bid * VT;
        const int vL = vbase + 2 * lane;        // iv 0,1
        const int vH = vbase + 64 + 2 * lane;   // iv 2,3

        float bz0 = (vL     < VOCAB) ? fc_bias[vL]     : 0.f;
        float bz1 = (vL + 1 < VOCAB) ? fc_bias[vL + 1] : 0.f;
        float bz2 = (vH     < VOCAB) ? fc_bias[vH]     : 0.f;
        float bz3 = (vH + 1 < VOCAB) ? fc_bias[vH + 1] : 0.f;
        ull acc[4][4];
#pragma unroll
        for (int bp = 0; bp < 4; bp++) {
            acc[0][bp] = pack2(bz0, bz0); acc[1][bp] = pack2(bz1, bz1);
            acc[2][bp] = pack2(bz2, bz2); acc[3][bp] = pack2(bz3, bz3);
        }

        const int fv  = tid & 127;   // fill vocab row
        const int fkh = tid >> 7;    // 0/1: which 16-k half
        const int fb  = tid & 63;    // fill batch
        const int fkq = tid >> 6;    // 0..3: 8-k group

        for (int k0 = 0; k0 < HID; k0 += KT) {
            {   // embed -> dup'd [half][k][v]
                const int gv = vbase + fv;
                ull* dst = &sm.l.e[fv >> 6][fkh * 16][fv & 63];
                if (gv < VOCAB) {
                    const float4* src = (const float4*)(embed + (size_t)gv * HID + k0 + fkh * 16);
#pragma unroll
                    for (int jj = 0; jj < 4; jj++) {
                        float4 f = src[jj];
                        dst[(4 * jj + 0) * 64] = pack2(f.x, f.x);
                        dst[(4 * jj + 1) * 64] = pack2(f.y, f.y);
                        dst[(4 * jj + 2) * 64] = pack2(f.z, f.z);
                        dst[(4 * jj + 3) * 64] = pack2(f.w, f.w);
                    }
                } else {
#pragma unroll
                    for (int jj = 0; jj < 16; jj++) dst[jj * 64] = 0ull;
                }
            }
            {   // h_rnn -> [k][b]
                const float4* hsrc = (const float4*)(g_hrnn + (size_t)fb * HID + k0 + fkq * 8);
                float* hd = &sm.l.h[fkq * 8][fb];
#pragma unroll
                for (int jj = 0; jj < 2; jj++) {
                    float4 f = hsrc[jj];
                    hd[(4 * jj + 0) * 64] = f.x; hd[(4 * jj + 1) * 64] = f.y;
                    hd[(4 * jj + 2) * 64] = f.z; hd[(4 * jj + 3) * 64] = f.w;
                }
            }
            __syncthreads();
#pragma unroll 8
            for (int k = 0; k < KT; k++) {
                ulonglong2 eL = *(const ulonglong2*)&sm.l.e[0][k][2 * lane];
                ulonglong2 eH = *(const ulonglong2*)&sm.l.e[1][k][2 * lane];
                ulonglong2 hA = *(const ulonglong2*)&sm.l.h[k][8 * warp];
                ulonglong2 hB = *(const ulonglong2*)&sm.l.h[k][8 * warp + 4];
                acc[0][0] = fma2(eL.x, hA.x, acc[0][0]); acc[0][1] = fma2(eL.x, hA.y, acc[0][1]);
                acc[0][2] = fma2(eL.x, hB.x, acc[0][2]); acc[0][3] = fma2(eL.x, hB.y, acc[0][3]);
                acc[1][0] = fma2(eL.y, hA.x, acc[1][0]); acc[1][1] = fma2(eL.y, hA.y, acc[1][1]);
                acc[1][2] = fma2(eL.y, hB.x, acc[1][2]); acc[1][3] = fma2(eL.y, hB.y, acc[1][3]);
                acc[2][0] = fma2(eH.x, hA.x, acc[2][0]); acc[2][1] = fma2(eH.x, hA.y, acc[2][1]);
                acc[2][2] = fma2(eH.x, hB.x, acc[2][2]); acc[2][3] = fma2(eH.x, hB.y, acc[2][3]);
                acc[3][0] = fma2(eH.y, hA.x, acc[3][0]); acc[3][1] = fma2(eH.y, hA.y, acc[3][1]);
                acc[3][2] = fma2(eH.y, hB.x, acc[3][2]); acc[3][3] = fma2(eH.y, hB.y, acc[3][3]);
            }
            __syncthreads();
        }

        // epilogue: store logits + per-batch argmax candidates (v ascending)
        float pv[8]; int pi[8];
#pragma unroll
        for (int bp = 0; bp < 4; bp++) {
            float l0e, l0o, l1e, l1o, l2e, l2o, l3e, l3o;
            unpack2(acc[0][bp], l0e, l0o);
            unpack2(acc[1][bp], l1e, l1o);
            unpack2(acc[2][bp], l2e, l2o);
            unpack2(acc[3][bp], l3e, l3o);
            const int be = 8 * warp + 2 * bp, bo = be + 1;
            if (vL < VOCAB) {
                *(float2*)&out_step[(size_t)be * VOCAB + vL] = make_float2(l0e, l1e);
                *(float2*)&out_step[(size_t)bo * VOCAB + vL] = make_float2(l0o, l1o);
            }
            if (vH < VOCAB) {
                *(float2*)&out_step[(size_t)be * VOCAB + vH] = make_float2(l2e, l3e);
                *(float2*)&out_step[(size_t)bo * VOCAB + vH] = make_float2(l2o, l3o);
            }
            float bv = NEG_INF; int bx = 0x7fffffff;
            if (vL < VOCAB) {
                if (l0e > bv) { bv = l0e; bx = vL; }
                if (l1e > bv) { bv = l1e; bx = vL + 1; }
            }
            if (vH < VOCAB) {
                if (l2e > bv) { bv = l2e; bx = vH; }
                if (l3e > bv) { bv = l3e; bx = vH + 1; }
            }
            pv[2 * bp] = bv; pi[2 * bp] = bx;
            bv = NEG_INF; bx = 0x7fffffff;
            if (vL < VOCAB) {
                if (l0o > bv) { bv = l0o; bx = vL; }
                if (l1o > bv) { bv = l1o; bx = vL + 1; }
            }
            if (vH < VOCAB) {
                if (l2o > bv) { bv = l2o; bx = vH; }
                if (l3o > bv) { bv = l3o; bx = vH + 1; }
            }
            pv[2 * bp + 1] = bv; pi[2 * bp + 1] = bx;
        }
#pragma unroll
        for (int s = 0; s < 8; s++) {
            float v = pv[s]; int ix = pi[s];
#pragma unroll
            for (int off = 16; off > 0; off >>= 1) {
                float ov = __shfl_xor_sync(0xffffffffu, v, off);
                int   oi = __shfl_xor_sync(0xffffffffu, ix, off);
                if (ov > v || (ov == v && oi < ix)) { v = ov; ix = oi; }
            }
            if (lane == 0) {
                g_pmax[bid * 64 + 8 * warp + s] = v;
                g_pidx[bid * 64 + 8 * warp + s] = ix;
            }
        }
    } else {
        // ================= attention block (h or c) ===========================
        const int a     = bid - NLOG;
        const int bi    = a & 63;
        const int which = a >> 6;
        const float* vr = (which ? g_crnn : g_hrnn) + (size_t)bi * HID;
        for (int d = tid; d < HID; d += 256) sm.a.vv[d] = vr[d];
        __syncthreads();
        for (int s = warp; s < SRC; s += 8) {
            float acc = 0.f;
            const float* er = enc + ((size_t)s * BATCH + bi) * HID;
            for (int d = lane; d < HID; d += 32) acc += er[d] * sm.a.vv[d];
#pragma unroll
            for (int o = 16; o > 0; o >>= 1) acc += __shfl_xor_sync(0xffffffffu, acc, o);
            if (lane == 0) sm.a.sc[s] = acc * 0.04419417382415922f; // 1/sqrt(512)
        }
        __syncthreads();
        if (tid == 0) {
            float m = sm.a.sc[0];
            for (int s = 1; s < SRC; s++) m = fmaxf(m, sm.a.sc[s]);
            float sum = 0.f;
            for (int s = 0; s < SRC; s++) { float e = expf(sm.a.sc[s] - m); sm.a.sc[s] = e; sum += e; }
            sm.a.isum = 1.f / sum;
        }
        __syncthreads();
        const float isum = sm.a.isum;
        float* dst = (which ? g_c : g_h) + (size_t)bi * HID;
        for (int d = tid; d < HID; d += 256) {
            float acc = 0.f;
#pragma unroll 10
            for (int s = 0; s < SRC; s++) acc += sm.a.sc[s] * enc[((size_t)s * BATCH + bi) * HID + d];
            dst[d] = acc * isum + sm.a.vv[d];
        }
    }

    // ================= last-block-done final argmax ===========================
    __threadfence();
    __syncthreads();
    if (tid == 0) {
        int old = atomicAdd(&g_done, 1);
        s_last = (old == (int)gridDim.x - 1);
    }
    __syncthreads();
    if (s_last) {
        const int b = tid & 63, grp = tid >> 6;
        float bv = NEG_INF; int bx = 0x7fffffff;
        for (int p = grp; p < NLOG; p += 4) {
            float v = g_pmax[p * 64 + b];
            int  ix = g_pidx[p * 64 + b];
            if (v > bv || (v == bv && ix < bx)) { bv = v; bx = ix; }
        }
        __syncthreads();   // all threads past union reuse of sm before writing sm.m
        sm.m.sv[tid] = bv; sm.m.si[tid] = bx;
        __syncthreads();
        if (tid < 64) {
            for (int g = 1; g < 4; g++) {
                float v = sm.m.sv[tid + 64 * g];
                int  ix = sm.m.si[tid + 64 * g];
                if (v > bv || (v == bv && ix < bx)) { bv = v; bx = ix; }
            }
            g_tok[b] = bx;
            if (write_tok) out_tok[b * STEPS + step] = (float)bx;
        }
        if (tid == 0) g_done = 0;
    }
}

// ---------------- launch: 1 init + 31 x (lstm, fused) -----------------------
extern "C" void kernel_launch(void* const* d_in, const int* in_sizes, int n_in,
                              void* d_out, int out_size) {
    const float* embed   = (const float*)d_in[0];
    const float* fc_bias = (const float*)d_in[1];
    const float* w_ih    = (const float*)d_in[2];
    const float* w_hh    = (const float*)d_in[3];
    const float* b_ih    = (const float*)d_in[4];
    const float* b_hh    = (const float*)d_in[5];
    const float* enc     = (const float*)d_in[6];
    const float* h0      = (const float*)d_in[7];
    const float* c0      = (const float*)d_in[8];
    const int*   t0      = (const int*)d_in[9];
    float* out = (float*)d_out;

    const long long LT = (long long)STEPS * BATCH * VOCAB;  // 99,200,000
    int write_tok = ((long long)out_size >= LT + (long long)BATCH * STEPS) ? 1 : 0;
    float* out_tok = out + LT;

    k_init<<<32, 256>>>(h0, c0, t0);
    for (int t = 0; t < STEPS; t++) {
        k_lstm<<<64, 256>>>(embed, w_ih, w_hh, b_ih, b_hh);
        k_fused<<<NLOG + 128, 256>>>(embed, fc_bias, enc,
                                     out + (long long)t * BATCH * VOCAB,
                                     out_tok, t, write_tok);
    }
}